// round 14
// baseline (speedup 1.0000x reference)
#include <cuda_runtime.h>
#include <cuda_fp16.h>
#include <math.h>
#include <stdint.h>

#define D_MODEL 1024
#define NHEADS 16
#define HDIM 64
#define BATCH 2
#define SEQ 2048
#define MTOT (BATCH * SEQ)   // 4096 rows

// -------- scratch (allocation-free rule: __device__ globals) --------
__device__ __half g_Xh[MTOT * D_MODEL];
__device__ __half g_Xl[MTOT * D_MODEL];
__device__ __half g_Wh[3 * D_MODEL * D_MODEL];
__device__ __half g_Wl[3 * D_MODEL * D_MODEL];
__device__ __half g_Qhi[MTOT * D_MODEL];
__device__ __half g_Qlo[MTOT * D_MODEL];
__device__ __half g_Khi[MTOT * D_MODEL];
__device__ __half g_Klo[MTOT * D_MODEL];
__device__ __half g_Vhi[MTOT * D_MODEL];

// ============================================================================
// helpers
// ============================================================================
__device__ __forceinline__ uint32_t smem_u32(const void* p) {
    uint32_t a;
    asm("{ .reg .u64 t; cvta.to.shared.u64 t, %1; cvt.u32.u64 %0, t; }"
        : "=r"(a) : "l"(p));
    return a;
}
__device__ __forceinline__ void ldsm4(uint32_t* r, uint32_t addr) {
    asm volatile("ldmatrix.sync.aligned.m8n8.x4.shared.b16 {%0,%1,%2,%3}, [%4];"
                 : "=r"(r[0]), "=r"(r[1]), "=r"(r[2]), "=r"(r[3]) : "r"(addr));
}
__device__ __forceinline__ void ldsm4t(uint32_t* r, uint32_t addr) {
    asm volatile("ldmatrix.sync.aligned.m8n8.x4.trans.shared.b16 {%0,%1,%2,%3}, [%4];"
                 : "=r"(r[0]), "=r"(r[1]), "=r"(r[2]), "=r"(r[3]) : "r"(addr));
}
__device__ __forceinline__ void mma16816(float* d, const uint32_t* a,
                                         uint32_t b0, uint32_t b1) {
    asm volatile(
        "mma.sync.aligned.m16n8k16.row.col.f32.f16.f16.f32 "
        "{%0,%1,%2,%3}, {%4,%5,%6,%7}, {%8,%9}, {%0,%1,%2,%3};"
        : "+f"(d[0]), "+f"(d[1]), "+f"(d[2]), "+f"(d[3])
        : "r"(a[0]), "r"(a[1]), "r"(a[2]), "r"(a[3]), "r"(b0), "r"(b1));
}
__device__ __forceinline__ void cpa16(uint32_t s, const void* g) {
    asm volatile("cp.async.cg.shared.global [%0], [%1], 16;" :: "r"(s), "l"(g));
}
#define CPA_COMMIT() asm volatile("cp.async.commit_group;" ::: "memory")
#define CPA_WAIT1() asm volatile("cp.async.wait_group 1;" ::: "memory")
#define CPA_WAIT0() asm volatile("cp.async.wait_group 0;" ::: "memory")

__device__ __forceinline__ void split_store2h(__half* hi, __half* lo,
                                              float a, float b) {
    __half ha = __float2half_rn(a), hb = __float2half_rn(b);
    __half2 h; h.x = ha; h.y = hb;
    *reinterpret_cast<__half2*>(hi) = h;
    if (lo) {
        __half2 l;
        l.x = __float2half_rn(a - __half2float(ha));
        l.y = __float2half_rn(b - __half2float(hb));
        *reinterpret_cast<__half2*>(lo) = l;
    }
}

// ============================================================================
// Split fp32 -> fp16 hi/lo
// ============================================================================
__device__ __forceinline__ void split_body(const float* __restrict__ src,
                                           __half* __restrict__ hi,
                                           __half* __restrict__ lo, int i) {
    float4 v = reinterpret_cast<const float4*>(src)[i];
    __half ha = __float2half_rn(v.x), hb = __float2half_rn(v.y);
    __half hc = __float2half_rn(v.z), hd = __float2half_rn(v.w);
    __half2 h0; h0.x = ha; h0.y = hb;
    __half2 h1; h1.x = hc; h1.y = hd;
    uint2 hu; hu.x = *reinterpret_cast<uint32_t*>(&h0);
    hu.y = *reinterpret_cast<uint32_t*>(&h1);
    reinterpret_cast<uint2*>(hi)[i] = hu;
    __half2 l0, l1;
    l0.x = __float2half_rn(v.x - __half2float(ha));
    l0.y = __float2half_rn(v.y - __half2float(hb));
    l1.x = __float2half_rn(v.z - __half2float(hc));
    l1.y = __float2half_rn(v.w - __half2float(hd));
    uint2 lu; lu.x = *reinterpret_cast<uint32_t*>(&l0);
    lu.y = *reinterpret_cast<uint32_t*>(&l1);
    reinterpret_cast<uint2*>(lo)[i] = lu;
}

__global__ __launch_bounds__(256)
void split_x(const float* __restrict__ src, __half* __restrict__ hi,
             __half* __restrict__ lo) {
    split_body(src, hi, lo, blockIdx.x * 256 + threadIdx.x);
}

__global__ __launch_bounds__(256)
void split_w(const float* __restrict__ wq, const float* __restrict__ wk,
             const float* __restrict__ wv, __half* __restrict__ hi,
             __half* __restrict__ lo) {
    const int mat = blockIdx.y;
    const float* src = (mat == 0) ? wq : (mat == 1 ? wk : wv);
    const size_t off4 = (size_t)mat * (D_MODEL * D_MODEL / 4);
    split_body(src, hi + off4 * 4, lo + off4 * 4, blockIdx.x * 256 + threadIdx.x);
}

// ============================================================================
// HMMA QKV projection GEMM. BM=128, BN=128, BK=32, 8 warps (4m x 2n),
// 3-pass fp16 split, cp.async double buffer. 64KB smem + <=128 regs
// -> 2 CTAs/SM (4 warps/SMSP hides RAW/LDSM latency).
// A tile: 128r x 32c (64B rows, granule swizzle g^((r>>1)&3)).
// B tile: 32r x 128c (256B rows, granule swizzle g^(r&7)).
// ============================================================================
#define GOF_AH 0
#define GOF_AL 8192
#define GOF_BH 16384
#define GOF_BL 24576
#define GBUF_BYTES 32768
#define GEMM_SMEM (2 * GBUF_BYTES)   // 65536

__global__ __launch_bounds__(256, 2)
void qkv_hmma(const __half* __restrict__ xh, const __half* __restrict__ xl,
              const __half* __restrict__ Wh_all, const __half* __restrict__ Wl_all,
              const float* __restrict__ bq, const float* __restrict__ bk,
              const float* __restrict__ bv,
              __half* __restrict__ qh, __half* __restrict__ ql,
              __half* __restrict__ kh, __half* __restrict__ kl,
              __half* __restrict__ vh) {
    extern __shared__ char smc[];
    const uint32_t sb = smem_u32(smc);
    const int tid = threadIdx.x;
    const int w = tid >> 5;
    const int L = tid & 31;
    const int nb = blockIdx.x;
    const int mat = nb >> 3;
    const int n0 = (nb & 7) * 128;
    const int m0 = blockIdx.y * 128;
    const int wm = w & 3, wn = w >> 2;

    const __half* Wh = Wh_all + (size_t)mat * D_MODEL * D_MODEL;
    const __half* Wl = Wl_all + (size_t)mat * D_MODEL * D_MODEL;
    const float* bias = (mat == 0) ? bq : (mat == 1 ? bk : bv);
    __half* Chi = (mat == 0) ? qh : (mat == 1 ? kh : vh);
    __half* Clo = (mat == 0) ? ql : (mat == 1 ? kl : (__half*)0);

    // cp.async coords: A 128 rows x 4 granules (2/thread); B 32 rows x 16 (2/thread)
    const int ar = tid >> 1;
    const int ag0 = (tid & 1) * 2;
    const int br = tid >> 3;
    const int bg0 = (tid & 7) * 2;

    auto issue = [&](int buf, int kc) {
        uint32_t base = sb + buf * GBUF_BYTES;
        const __half* ah_g = xh + (size_t)(m0 + ar) * D_MODEL + kc * 32;
        const __half* al_g = xl + (size_t)(m0 + ar) * D_MODEL + kc * 32;
#pragma unroll
        for (int gi = 0; gi < 2; gi++) {
            int g = ag0 + gi;
            uint32_t off = ar * 64 + (((g ^ ((ar >> 1) & 3)) & 3) << 4);
            cpa16(base + GOF_AH + off, ah_g + g * 8);
            cpa16(base + GOF_AL + off, al_g + g * 8);
        }
        const __half* bh_g = Wh + (size_t)(kc * 32 + br) * D_MODEL + n0;
        const __half* bl_g = Wl + (size_t)(kc * 32 + br) * D_MODEL + n0;
#pragma unroll
        for (int gi = 0; gi < 2; gi++) {
            int g = bg0 + gi;
            uint32_t off = br * 256 + (((g ^ (br & 7)) & 15) << 4);
            cpa16(base + GOF_BH + off, bh_g + g * 8);
            cpa16(base + GOF_BL + off, bl_g + g * 8);
        }
    };

    float acc[2][8][4];
#pragma unroll
    for (int i = 0; i < 2; i++)
#pragma unroll
        for (int j = 0; j < 8; j++)
#pragma unroll
            for (int e = 0; e < 4; e++) acc[i][j][e] = 0.0f;

    issue(0, 0);
    CPA_COMMIT();

    const int lrow = L & 15;
    const int lcg = (L >> 4) & 1;

    for (int kc = 0; kc < 32; kc++) {
        if (kc + 1 < 32) { issue((kc + 1) & 1, kc + 1); CPA_COMMIT(); CPA_WAIT1(); }
        else { CPA_WAIT0(); }
        __syncthreads();

        uint32_t base = sb + (kc & 1) * GBUF_BYTES;
#pragma unroll
        for (int ks = 0; ks < 2; ks++) {
            uint32_t ah[2][4], al[2][4];
#pragma unroll
            for (int mt = 0; mt < 2; mt++) {
                int arow = wm * 32 + mt * 16 + lrow;
                int ga = ks * 2 + lcg;
                uint32_t off = arow * 64 + (((ga ^ ((arow >> 1) & 3)) & 3) << 4);
                ldsm4(ah[mt], base + GOF_AH + off);
                ldsm4(al[mt], base + GOF_AL + off);
            }
            int brow = ks * 16 + lrow;
            uint32_t brbase = brow * 256;
            int brx = brow & 7;
            // process b in halves (nt2 pairs) to cap registers
#pragma unroll
            for (int hf = 0; hf < 2; hf++) {
                uint32_t bh[2][4], bl[2][4];
#pragma unroll
                for (int j = 0; j < 2; j++) {
                    int nt2 = hf * 2 + j;
                    int g = wn * 8 + nt2 * 2 + lcg;
                    uint32_t off = brbase + (((g ^ brx) & 15) << 4);
                    ldsm4t(bh[j], base + GOF_BH + off);
                    ldsm4t(bl[j], base + GOF_BL + off);
                }
                // pass-major over this half: acc reuse distance 8
#pragma unroll
                for (int j = 0; j < 2; j++)
#pragma unroll
                    for (int mt = 0; mt < 2; mt++) {
                        int nt2 = hf * 2 + j;
                        mma16816(acc[mt][nt2 * 2],     ah[mt], bh[j][0], bh[j][1]);
                        mma16816(acc[mt][nt2 * 2 + 1], ah[mt], bh[j][2], bh[j][3]);
                    }
#pragma unroll
                for (int j = 0; j < 2; j++)
#pragma unroll
                    for (int mt = 0; mt < 2; mt++) {
                        int nt2 = hf * 2 + j;
                        mma16816(acc[mt][nt2 * 2],     al[mt], bh[j][0], bh[j][1]);
                        mma16816(acc[mt][nt2 * 2 + 1], al[mt], bh[j][2], bh[j][3]);
                    }
#pragma unroll
                for (int j = 0; j < 2; j++)
#pragma unroll
                    for (int mt = 0; mt < 2; mt++) {
                        int nt2 = hf * 2 + j;
                        mma16816(acc[mt][nt2 * 2],     ah[mt], bl[j][0], bl[j][1]);
                        mma16816(acc[mt][nt2 * 2 + 1], ah[mt], bl[j][2], bl[j][3]);
                    }
            }
        }
        __syncthreads();
    }

#pragma unroll
    for (int mt = 0; mt < 2; mt++) {
        int r = m0 + wm * 32 + mt * 16 + (L >> 2);
#pragma unroll
        for (int nt = 0; nt < 8; nt++) {
            int c = n0 + wn * 64 + nt * 8 + 2 * (L & 3);
            float b0 = bias[c], b1 = bias[c + 1];
            size_t o0 = (size_t)r * D_MODEL + c;
            size_t o1 = o0 + 8 * D_MODEL;
            split_store2h(Chi + o0, Clo ? Clo + o0 : (__half*)0,
                          acc[mt][nt][0] + b0, acc[mt][nt][1] + b1);
            split_store2h(Chi + o1, Clo ? Clo + o1 : (__half*)0,
                          acc[mt][nt][2] + b0, acc[mt][nt][3] + b1);
        }
    }
}

// ============================================================================
// HMMA flash attention, BKV=64: cp.async double-buffered K/V, fp16 split Q/K
// 3-pass QK^T, online softmax, fp16 1-pass PV, O in registers.
// 96KB smem + ~110 regs -> 2 CTAs/SM. No manual prefetch (occupancy hides).
// Layout: [0,16K) Qhi  [16K,32K) Qlo  [32K,48K) P (128r x 128B)
//         [48K,72K) KV buf0 {Khi 8K, Klo 8K, Vhi 8K}  [72K,96K) KV buf1
// ============================================================================
#define SQHI 0
#define SQLO 16384
#define SPS  32768
#define SKV0 49152
#define KVBUF 24576
#define ATTN_SMEM (SKV0 + 2 * KVBUF)   // 98304

__global__ __launch_bounds__(256, 2)
void attn_hmma(const __half* __restrict__ Qhi, const __half* __restrict__ Qlo,
               const __half* __restrict__ Khi, const __half* __restrict__ Klo,
               const __half* __restrict__ Vhi, float* __restrict__ Out) {
    extern __shared__ char smc[];
    const uint32_t sb = smem_u32(smc);
    const int tid = threadIdx.x;
    const int w = tid >> 5;
    const int L = tid & 31;
    const int b = blockIdx.y >> 4, h = blockIdx.y & 15;
    const int q0 = blockIdx.x * 128;
    const size_t rowbase = (size_t)b * SEQ;

    // KV cp.async coords: 64 rows x 8 granules per layer, 2 granules/thread
    const int kvr = tid >> 2;
    const int kvg0 = (tid & 3) * 2;

    auto kvissue = [&](int buf, int t) {
        uint32_t base = sb + SKV0 + buf * KVBUF;
        const __half* kh_g = Khi + (rowbase + t * 64 + kvr) * D_MODEL + h * HDIM;
        const __half* kl_g = Klo + (rowbase + t * 64 + kvr) * D_MODEL + h * HDIM;
        const __half* vh_g = Vhi + (rowbase + t * 64 + kvr) * D_MODEL + h * HDIM;
#pragma unroll
        for (int gi = 0; gi < 2; gi++) {
            int g = kvg0 + gi;
            uint32_t off = kvr * 128 + (((g ^ (kvr & 7)) & 7) << 4);
            cpa16(base + off,         kh_g + g * 8);
            cpa16(base + 8192 + off,  kl_g + g * 8);
            cpa16(base + 16384 + off, vh_g + g * 8);
        }
    };

    // ---- load Q hi/lo (synchronous; one-time) ----
    const __half* qh_g = Qhi + (rowbase + q0) * D_MODEL + h * HDIM;
    const __half* ql_g = Qlo + (rowbase + q0) * D_MODEL + h * HDIM;
#pragma unroll
    for (int i = 0; i < 4; i++) {
        int vid = i * 256 + tid;
        int r = vid >> 3;
        int g = vid & 7;
        uint32_t off = r * 128 + ((g ^ (r & 7)) << 4);
        *(uint4*)(smc + SQHI + off) = *(const uint4*)(qh_g + (size_t)r * D_MODEL + g * 8);
        *(uint4*)(smc + SQLO + off) = *(const uint4*)(ql_g + (size_t)r * D_MODEL + g * 8);
    }
    kvissue(0, 0);
    CPA_COMMIT();
    __syncthreads();

    float S[8][4], O[8][4];
#pragma unroll
    for (int i = 0; i < 8; i++)
#pragma unroll
        for (int j = 0; j < 4; j++) O[i][j] = 0.0f;
    float l0 = 0.0f, l1 = 0.0f, m0 = -INFINITY, m1 = -INFINITY;

    const int arow = w * 16 + (L & 15);            // Q/P A-operand row
    const int acg = (L >> 4) & 1;
    const int brow_off = (L & 7) + ((L & 16) ? 8 : 0);  // K B-frag row offset
    const int bcg = (L >> 3) & 1;
    const int vrow_off = (L & 7) + ((L & 8) ? 8 : 0);   // V^T row offset
    const int prow = w * 16 + (L >> 2);            // softmax-owned row
    const int pxr = prow & 7;
    const int arx = arow & 7;

    for (int t = 0; t < 32; t++) {
        const int cur = t & 1;
        if (t + 1 < 32) { kvissue(1 - cur, t + 1); CPA_COMMIT(); CPA_WAIT1(); }
        else { CPA_WAIT0(); }
        __syncthreads();

        const uint32_t khb = sb + SKV0 + cur * KVBUF;
        const uint32_t klb = khb + 8192;
        const uint32_t vhb = khb + 16384;

        // ---- S = Q K^T (3-pass); ks outer so qf loads amortize over np ----
#pragma unroll
        for (int i = 0; i < 8; i++) {
            S[i][0] = 0.0f; S[i][1] = 0.0f; S[i][2] = 0.0f; S[i][3] = 0.0f;
        }
#pragma unroll
        for (int ks = 0; ks < 4; ks++) {
            uint32_t qfh[4], qfl[4];
            uint32_t qoff = arow * 128 + ((((ks * 2 + acg) ^ arx) & 7) << 4);
            ldsm4(qfh, sb + SQHI + qoff);
            ldsm4(qfl, sb + SQLO + qoff);
#pragma unroll
            for (int np = 0; np < 4; np++) {
                int brow = np * 16 + brow_off;
                uint32_t offb = brow * 128 + ((((ks * 2 + bcg) ^ (brow & 7)) & 7) << 4);
                uint32_t kbh[4], kbl[4];
                ldsm4(kbh, khb + offb);
                ldsm4(kbl, klb + offb);
                mma16816(S[2 * np],     qfh, kbh[0], kbh[1]);
                mma16816(S[2 * np + 1], qfh, kbh[2], kbh[3]);
                mma16816(S[2 * np],     qfl, kbh[0], kbh[1]);
                mma16816(S[2 * np + 1], qfl, kbh[2], kbh[3]);
                mma16816(S[2 * np],     qfh, kbl[0], kbl[1]);
                mma16816(S[2 * np + 1], qfh, kbl[2], kbl[3]);
            }
        }

        // ---- online softmax (warp-local rows) ----
        float tm0 = -INFINITY, tm1 = -INFINITY;
#pragma unroll
        for (int i = 0; i < 8; i++) {
            tm0 = fmaxf(tm0, fmaxf(S[i][0], S[i][1]));
            tm1 = fmaxf(tm1, fmaxf(S[i][2], S[i][3]));
        }
        tm0 = fmaxf(tm0, __shfl_xor_sync(0xffffffffu, tm0, 1));
        tm0 = fmaxf(tm0, __shfl_xor_sync(0xffffffffu, tm0, 2));
        tm1 = fmaxf(tm1, __shfl_xor_sync(0xffffffffu, tm1, 1));
        tm1 = fmaxf(tm1, __shfl_xor_sync(0xffffffffu, tm1, 2));
        float mn0 = fmaxf(m0, tm0), mn1 = fmaxf(m1, tm1);
        float sc0 = __expf(m0 - mn0), sc1 = __expf(m1 - mn1);
        l0 *= sc0; l1 *= sc1;
        m0 = mn0; m1 = mn1;
#pragma unroll
        for (int i = 0; i < 8; i++) {
            O[i][0] *= sc0; O[i][1] *= sc0;
            O[i][2] *= sc1; O[i][3] *= sc1;
        }
        {
            uint32_t pb0 = (uint32_t)(SPS + prow * 128 + 4 * (L & 3));
            uint32_t pb1 = pb0 + 8 * 128;
#pragma unroll
            for (int nt = 0; nt < 8; nt++) {
                float p0 = __expf(S[nt][0] - mn0);
                float p1 = __expf(S[nt][1] - mn0);
                float p2 = __expf(S[nt][2] - mn1);
                float p3 = __expf(S[nt][3] - mn1);
                l0 += p0 + p1;
                l1 += p2 + p3;
                __half2 h01 = __floats2half2_rn(p0, p1);
                __half2 h23 = __floats2half2_rn(p2, p3);
                uint32_t gsh = (uint32_t)(((nt ^ pxr) & 7) << 4);
                *(uint32_t*)(smc + pb0 + gsh) = *reinterpret_cast<uint32_t*>(&h01);
                *(uint32_t*)(smc + pb1 + gsh) = *reinterpret_cast<uint32_t*>(&h23);
            }
        }
        __syncwarp();

        // ---- O += P V (1-pass fp16) ----
#pragma unroll
        for (int ks = 0; ks < 4; ks++) {
            uint32_t pa[4];
            uint32_t poff = arow * 128 + ((((ks * 2 + acg) ^ arx) & 7) << 4);
            ldsm4(pa, sb + SPS + poff);
#pragma unroll
            for (int np = 0; np < 4; np++) {
                int vrow = ks * 16 + vrow_off;
                uint32_t voff = vrow * 128 +
                    ((((np * 2 + ((L >> 4) & 1)) ^ (vrow & 7)) & 7) << 4);
                uint32_t vb[4];
                ldsm4t(vb, vhb + voff);
                mma16816(O[2 * np],     pa, vb[0], vb[1]);
                mma16816(O[2 * np + 1], pa, vb[2], vb[3]);
            }
        }
        __syncthreads();   // buf[cur] fully consumed before next prefetch overwrites
    }

    // ---- finalize ----
    l0 += __shfl_xor_sync(0xffffffffu, l0, 1);
    l0 += __shfl_xor_sync(0xffffffffu, l0, 2);
    l1 += __shfl_xor_sync(0xffffffffu, l1, 1);
    l1 += __shfl_xor_sync(0xffffffffu, l1, 2);
    float i0 = 1.0f / l0, i1 = 1.0f / l1;
    int r0 = q0 + prow;
    float* o0 = Out + (rowbase + r0) * D_MODEL + h * HDIM + 2 * (L & 3);
    float* o1 = o0 + 8 * D_MODEL;
#pragma unroll
    for (int nt = 0; nt < 8; nt++) {
        float2 a; a.x = O[nt][0] * i0; a.y = O[nt][1] * i0;
        float2 c; c.x = O[nt][2] * i1; c.y = O[nt][3] * i1;
        *(float2*)(o0 + nt * 8) = a;
        *(float2*)(o1 + nt * 8) = c;
    }
}

// ============================================================================
extern "C" void kernel_launch(void* const* d_in, const int* in_sizes, int n_in,
                              void* d_out, int out_size) {
    (void)in_sizes; (void)n_in; (void)out_size;
    const float* x  = (const float*)d_in[0];
    const float* Wq = (const float*)d_in[1];
    const float* bq = (const float*)d_in[2];
    const float* Wk = (const float*)d_in[3];
    const float* bk = (const float*)d_in[4];
    const float* Wv = (const float*)d_in[5];
    const float* bv = (const float*)d_in[6];
    float* out = (float*)d_out;

    __half *xh, *xl, *wh, *wl, *qh, *ql, *kh, *kl, *vh;
    cudaGetSymbolAddress((void**)&xh, g_Xh);
    cudaGetSymbolAddress((void**)&xl, g_Xl);
    cudaGetSymbolAddress((void**)&wh, g_Wh);
    cudaGetSymbolAddress((void**)&wl, g_Wl);
    cudaGetSymbolAddress((void**)&qh, g_Qhi);
    cudaGetSymbolAddress((void**)&ql, g_Qlo);
    cudaGetSymbolAddress((void**)&kh, g_Khi);
    cudaGetSymbolAddress((void**)&kl, g_Klo);
    cudaGetSymbolAddress((void**)&vh, g_Vhi);

    // Unconditional (idempotent): no static guards allowed in kernel_launch.
    cudaFuncSetAttribute(qkv_hmma, cudaFuncAttributeMaxDynamicSharedMemorySize,
                         GEMM_SMEM);
    cudaFuncSetAttribute(attn_hmma, cudaFuncAttributeMaxDynamicSharedMemorySize,
                         ATTN_SMEM);

    // 1) split inputs to fp16 hi/lo
    const int xn4 = MTOT * D_MODEL / 4;       // 1048576
    const int wn4 = D_MODEL * D_MODEL / 4;    // 262144
    split_x<<<xn4 / 256, 256>>>(x, xh, xl);
    dim3 wgrid(wn4 / 256, 3);
    split_w<<<wgrid, 256>>>(Wq, Wk, Wv, wh, wl);

    // 2) HMMA QKV projection
    dim3 ggrid(24, MTOT / 128);
    qkv_hmma<<<ggrid, 256, GEMM_SMEM>>>(xh, xl, wh, wl, bq, bk, bv,
                                        qh, ql, kh, kl, vh);

    // 3) HMMA flash attention
    dim3 agrid(SEQ / 128, BATCH * NHEADS);
    attn_hmma<<<agrid, 256, ATTN_SMEM>>>(qh, ql, kh, kl, vh, out);
}

// round 15
// speedup vs baseline: 1.0004x; 1.0004x over previous
#include <cuda_runtime.h>
#include <cuda_fp16.h>
#include <math.h>
#include <stdint.h>

#define D_MODEL 1024
#define NHEADS 16
#define HDIM 64
#define BATCH 2
#define SEQ 2048
#define MTOT (BATCH * SEQ)   // 4096 rows

// -------- scratch (allocation-free rule: __device__ globals) --------
__device__ __half g_Xh[MTOT * D_MODEL];
__device__ __half g_Xl[MTOT * D_MODEL];
__device__ __half g_Wh[3 * D_MODEL * D_MODEL];
__device__ __half g_Wl[3 * D_MODEL * D_MODEL];
__device__ __half g_Qhi[MTOT * D_MODEL];
__device__ __half g_Qlo[MTOT * D_MODEL];
__device__ __half g_Khi[MTOT * D_MODEL];
__device__ __half g_Klo[MTOT * D_MODEL];
__device__ __half g_Vhi[MTOT * D_MODEL];

// ============================================================================
// helpers
// ============================================================================
__device__ __forceinline__ uint32_t smem_u32(const void* p) {
    uint32_t a;
    asm("{ .reg .u64 t; cvta.to.shared.u64 t, %1; cvt.u32.u64 %0, t; }"
        : "=r"(a) : "l"(p));
    return a;
}
__device__ __forceinline__ void ldsm4(uint32_t* r, uint32_t addr) {
    asm volatile("ldmatrix.sync.aligned.m8n8.x4.shared.b16 {%0,%1,%2,%3}, [%4];"
                 : "=r"(r[0]), "=r"(r[1]), "=r"(r[2]), "=r"(r[3]) : "r"(addr));
}
__device__ __forceinline__ void ldsm4t(uint32_t* r, uint32_t addr) {
    asm volatile("ldmatrix.sync.aligned.m8n8.x4.trans.shared.b16 {%0,%1,%2,%3}, [%4];"
                 : "=r"(r[0]), "=r"(r[1]), "=r"(r[2]), "=r"(r[3]) : "r"(addr));
}
__device__ __forceinline__ void mma16816(float* d, const uint32_t* a,
                                         uint32_t b0, uint32_t b1) {
    asm volatile(
        "mma.sync.aligned.m16n8k16.row.col.f32.f16.f16.f32 "
        "{%0,%1,%2,%3}, {%4,%5,%6,%7}, {%8,%9}, {%0,%1,%2,%3};"
        : "+f"(d[0]), "+f"(d[1]), "+f"(d[2]), "+f"(d[3])
        : "r"(a[0]), "r"(a[1]), "r"(a[2]), "r"(a[3]), "r"(b0), "r"(b1));
}
__device__ __forceinline__ void cpa16(uint32_t s, const void* g) {
    asm volatile("cp.async.cg.shared.global [%0], [%1], 16;" :: "r"(s), "l"(g));
}
#define CPA_COMMIT() asm volatile("cp.async.commit_group;" ::: "memory")
#define CPA_WAIT1() asm volatile("cp.async.wait_group 1;" ::: "memory")
#define CPA_WAIT0() asm volatile("cp.async.wait_group 0;" ::: "memory")

__device__ __forceinline__ void split_store2h(__half* hi, __half* lo,
                                              float a, float b) {
    __half ha = __float2half_rn(a), hb = __float2half_rn(b);
    __half2 h; h.x = ha; h.y = hb;
    *reinterpret_cast<__half2*>(hi) = h;
    if (lo) {
        __half2 l;
        l.x = __float2half_rn(a - __half2float(ha));
        l.y = __float2half_rn(b - __half2float(hb));
        *reinterpret_cast<__half2*>(lo) = l;
    }
}

// ============================================================================
// Split fp32 -> fp16 hi/lo
// ============================================================================
__device__ __forceinline__ void split_body(const float* __restrict__ src,
                                           __half* __restrict__ hi,
                                           __half* __restrict__ lo, int i) {
    float4 v = reinterpret_cast<const float4*>(src)[i];
    __half ha = __float2half_rn(v.x), hb = __float2half_rn(v.y);
    __half hc = __float2half_rn(v.z), hd = __float2half_rn(v.w);
    __half2 h0; h0.x = ha; h0.y = hb;
    __half2 h1; h1.x = hc; h1.y = hd;
    uint2 hu; hu.x = *reinterpret_cast<uint32_t*>(&h0);
    hu.y = *reinterpret_cast<uint32_t*>(&h1);
    reinterpret_cast<uint2*>(hi)[i] = hu;
    __half2 l0, l1;
    l0.x = __float2half_rn(v.x - __half2float(ha));
    l0.y = __float2half_rn(v.y - __half2float(hb));
    l1.x = __float2half_rn(v.z - __half2float(hc));
    l1.y = __float2half_rn(v.w - __half2float(hd));
    uint2 lu; lu.x = *reinterpret_cast<uint32_t*>(&l0);
    lu.y = *reinterpret_cast<uint32_t*>(&l1);
    reinterpret_cast<uint2*>(lo)[i] = lu;
}

__global__ __launch_bounds__(256)
void split_x(const float* __restrict__ src, __half* __restrict__ hi,
             __half* __restrict__ lo) {
    split_body(src, hi, lo, blockIdx.x * 256 + threadIdx.x);
}

__global__ __launch_bounds__(256)
void split_w(const float* __restrict__ wq, const float* __restrict__ wk,
             const float* __restrict__ wv, __half* __restrict__ hi,
             __half* __restrict__ lo) {
    const int mat = blockIdx.y;
    const float* src = (mat == 0) ? wq : (mat == 1 ? wk : wv);
    const size_t off4 = (size_t)mat * (D_MODEL * D_MODEL / 4);
    split_body(src, hi + off4 * 4, lo + off4 * 4, blockIdx.x * 256 + threadIdx.x);
}

// ============================================================================
// HMMA QKV projection GEMM. BM=128, BN=128, BK=32, 8 warps (4m x 2n),
// 3-pass fp16 split, cp.async double buffer. 64KB smem + <=128 regs
// -> 2 CTAs/SM (4 warps/SMSP hides RAW/LDSM latency).
// A tile: 128r x 32c (64B rows, granule swizzle g^((r>>1)&3)).
// B tile: 32r x 128c (256B rows, granule swizzle g^(r&7)).
// ============================================================================
#define GOF_AH 0
#define GOF_AL 8192
#define GOF_BH 16384
#define GOF_BL 24576
#define GBUF_BYTES 32768
#define GEMM_SMEM (2 * GBUF_BYTES)   // 65536

__global__ __launch_bounds__(256, 2)
void qkv_hmma(const __half* __restrict__ xh, const __half* __restrict__ xl,
              const __half* __restrict__ Wh_all, const __half* __restrict__ Wl_all,
              const float* __restrict__ bq, const float* __restrict__ bk,
              const float* __restrict__ bv,
              __half* __restrict__ qh, __half* __restrict__ ql,
              __half* __restrict__ kh, __half* __restrict__ kl,
              __half* __restrict__ vh) {
    extern __shared__ char smc[];
    const uint32_t sb = smem_u32(smc);
    const int tid = threadIdx.x;
    const int w = tid >> 5;
    const int L = tid & 31;
    const int nb = blockIdx.x;
    const int mat = nb >> 3;
    const int n0 = (nb & 7) * 128;
    const int m0 = blockIdx.y * 128;
    const int wm = w & 3, wn = w >> 2;

    const __half* Wh = Wh_all + (size_t)mat * D_MODEL * D_MODEL;
    const __half* Wl = Wl_all + (size_t)mat * D_MODEL * D_MODEL;
    const float* bias = (mat == 0) ? bq : (mat == 1 ? bk : bv);
    __half* Chi = (mat == 0) ? qh : (mat == 1 ? kh : vh);
    __half* Clo = (mat == 0) ? ql : (mat == 1 ? kl : (__half*)0);

    // cp.async coords: A 128 rows x 4 granules (2/thread); B 32 rows x 16 (2/thread)
    const int ar = tid >> 1;
    const int ag0 = (tid & 1) * 2;
    const int br = tid >> 3;
    const int bg0 = (tid & 7) * 2;

    auto issue = [&](int buf, int kc) {
        uint32_t base = sb + buf * GBUF_BYTES;
        const __half* ah_g = xh + (size_t)(m0 + ar) * D_MODEL + kc * 32;
        const __half* al_g = xl + (size_t)(m0 + ar) * D_MODEL + kc * 32;
#pragma unroll
        for (int gi = 0; gi < 2; gi++) {
            int g = ag0 + gi;
            uint32_t off = ar * 64 + (((g ^ ((ar >> 1) & 3)) & 3) << 4);
            cpa16(base + GOF_AH + off, ah_g + g * 8);
            cpa16(base + GOF_AL + off, al_g + g * 8);
        }
        const __half* bh_g = Wh + (size_t)(kc * 32 + br) * D_MODEL + n0;
        const __half* bl_g = Wl + (size_t)(kc * 32 + br) * D_MODEL + n0;
#pragma unroll
        for (int gi = 0; gi < 2; gi++) {
            int g = bg0 + gi;
            uint32_t off = br * 256 + (((g ^ (br & 7)) & 15) << 4);
            cpa16(base + GOF_BH + off, bh_g + g * 8);
            cpa16(base + GOF_BL + off, bl_g + g * 8);
        }
    };

    float acc[2][8][4];
#pragma unroll
    for (int i = 0; i < 2; i++)
#pragma unroll
        for (int j = 0; j < 8; j++)
#pragma unroll
            for (int e = 0; e < 4; e++) acc[i][j][e] = 0.0f;

    issue(0, 0);
    CPA_COMMIT();

    const int lrow = L & 15;
    const int lcg = (L >> 4) & 1;

    for (int kc = 0; kc < 32; kc++) {
        if (kc + 1 < 32) { issue((kc + 1) & 1, kc + 1); CPA_COMMIT(); CPA_WAIT1(); }
        else { CPA_WAIT0(); }
        __syncthreads();

        uint32_t base = sb + (kc & 1) * GBUF_BYTES;
#pragma unroll
        for (int ks = 0; ks < 2; ks++) {
            uint32_t ah[2][4], al[2][4];
#pragma unroll
            for (int mt = 0; mt < 2; mt++) {
                int arow = wm * 32 + mt * 16 + lrow;
                int ga = ks * 2 + lcg;
                uint32_t off = arow * 64 + (((ga ^ ((arow >> 1) & 3)) & 3) << 4);
                ldsm4(ah[mt], base + GOF_AH + off);
                ldsm4(al[mt], base + GOF_AL + off);
            }
            int brow = ks * 16 + lrow;
            uint32_t brbase = brow * 256;
            int brx = brow & 7;
            // process b in halves (nt2 pairs) to cap registers
#pragma unroll
            for (int hf = 0; hf < 2; hf++) {
                uint32_t bh[2][4], bl[2][4];
#pragma unroll
                for (int j = 0; j < 2; j++) {
                    int nt2 = hf * 2 + j;
                    int g = wn * 8 + nt2 * 2 + lcg;
                    uint32_t off = brbase + (((g ^ brx) & 15) << 4);
                    ldsm4t(bh[j], base + GOF_BH + off);
                    ldsm4t(bl[j], base + GOF_BL + off);
                }
                // pass-major over this half: acc reuse distance 8
#pragma unroll
                for (int j = 0; j < 2; j++)
#pragma unroll
                    for (int mt = 0; mt < 2; mt++) {
                        int nt2 = hf * 2 + j;
                        mma16816(acc[mt][nt2 * 2],     ah[mt], bh[j][0], bh[j][1]);
                        mma16816(acc[mt][nt2 * 2 + 1], ah[mt], bh[j][2], bh[j][3]);
                    }
#pragma unroll
                for (int j = 0; j < 2; j++)
#pragma unroll
                    for (int mt = 0; mt < 2; mt++) {
                        int nt2 = hf * 2 + j;
                        mma16816(acc[mt][nt2 * 2],     al[mt], bh[j][0], bh[j][1]);
                        mma16816(acc[mt][nt2 * 2 + 1], al[mt], bh[j][2], bh[j][3]);
                    }
#pragma unroll
                for (int j = 0; j < 2; j++)
#pragma unroll
                    for (int mt = 0; mt < 2; mt++) {
                        int nt2 = hf * 2 + j;
                        mma16816(acc[mt][nt2 * 2],     ah[mt], bl[j][0], bl[j][1]);
                        mma16816(acc[mt][nt2 * 2 + 1], ah[mt], bl[j][2], bl[j][3]);
                    }
            }
        }
        __syncthreads();
    }

#pragma unroll
    for (int mt = 0; mt < 2; mt++) {
        int r = m0 + wm * 32 + mt * 16 + (L >> 2);
#pragma unroll
        for (int nt = 0; nt < 8; nt++) {
            int c = n0 + wn * 64 + nt * 8 + 2 * (L & 3);
            float b0 = bias[c], b1 = bias[c + 1];
            size_t o0 = (size_t)r * D_MODEL + c;
            size_t o1 = o0 + 8 * D_MODEL;
            split_store2h(Chi + o0, Clo ? Clo + o0 : (__half*)0,
                          acc[mt][nt][0] + b0, acc[mt][nt][1] + b1);
            split_store2h(Chi + o1, Clo ? Clo + o1 : (__half*)0,
                          acc[mt][nt][2] + b0, acc[mt][nt][3] + b1);
        }
    }
}

// ============================================================================
// HMMA flash attention, BKV=64: cp.async double-buffered K/V, fp16 split Q/K
// 3-pass QK^T, online softmax, fp16 1-pass PV, O in registers.
// 96KB smem + ~110 regs -> 2 CTAs/SM. No manual prefetch (occupancy hides).
// Layout: [0,16K) Qhi  [16K,32K) Qlo  [32K,48K) P (128r x 128B)
//         [48K,72K) KV buf0 {Khi 8K, Klo 8K, Vhi 8K}  [72K,96K) KV buf1
// ============================================================================
#define SQHI 0
#define SQLO 16384
#define SPS  32768
#define SKV0 49152
#define KVBUF 24576
#define ATTN_SMEM (SKV0 + 2 * KVBUF)   // 98304

__global__ __launch_bounds__(256, 2)
void attn_hmma(const __half* __restrict__ Qhi, const __half* __restrict__ Qlo,
               const __half* __restrict__ Khi, const __half* __restrict__ Klo,
               const __half* __restrict__ Vhi, float* __restrict__ Out) {
    extern __shared__ char smc[];
    const uint32_t sb = smem_u32(smc);
    const int tid = threadIdx.x;
    const int w = tid >> 5;
    const int L = tid & 31;
    const int b = blockIdx.y >> 4, h = blockIdx.y & 15;
    const int q0 = blockIdx.x * 128;
    const size_t rowbase = (size_t)b * SEQ;

    // KV cp.async coords: 64 rows x 8 granules per layer, 2 granules/thread
    const int kvr = tid >> 2;
    const int kvg0 = (tid & 3) * 2;

    auto kvissue = [&](int buf, int t) {
        uint32_t base = sb + SKV0 + buf * KVBUF;
        const __half* kh_g = Khi + (rowbase + t * 64 + kvr) * D_MODEL + h * HDIM;
        const __half* kl_g = Klo + (rowbase + t * 64 + kvr) * D_MODEL + h * HDIM;
        const __half* vh_g = Vhi + (rowbase + t * 64 + kvr) * D_MODEL + h * HDIM;
#pragma unroll
        for (int gi = 0; gi < 2; gi++) {
            int g = kvg0 + gi;
            uint32_t off = kvr * 128 + (((g ^ (kvr & 7)) & 7) << 4);
            cpa16(base + off,         kh_g + g * 8);
            cpa16(base + 8192 + off,  kl_g + g * 8);
            cpa16(base + 16384 + off, vh_g + g * 8);
        }
    };

    // ---- load Q hi/lo (synchronous; one-time) ----
    const __half* qh_g = Qhi + (rowbase + q0) * D_MODEL + h * HDIM;
    const __half* ql_g = Qlo + (rowbase + q0) * D_MODEL + h * HDIM;
#pragma unroll
    for (int i = 0; i < 4; i++) {
        int vid = i * 256 + tid;
        int r = vid >> 3;
        int g = vid & 7;
        uint32_t off = r * 128 + ((g ^ (r & 7)) << 4);
        *(uint4*)(smc + SQHI + off) = *(const uint4*)(qh_g + (size_t)r * D_MODEL + g * 8);
        *(uint4*)(smc + SQLO + off) = *(const uint4*)(ql_g + (size_t)r * D_MODEL + g * 8);
    }
    kvissue(0, 0);
    CPA_COMMIT();
    __syncthreads();

    float S[8][4], O[8][4];
#pragma unroll
    for (int i = 0; i < 8; i++)
#pragma unroll
        for (int j = 0; j < 4; j++) O[i][j] = 0.0f;
    float l0 = 0.0f, l1 = 0.0f, m0 = -INFINITY, m1 = -INFINITY;

    const int arow = w * 16 + (L & 15);            // Q/P A-operand row
    const int acg = (L >> 4) & 1;
    const int brow_off = (L & 7) + ((L & 16) ? 8 : 0);  // K B-frag row offset
    const int bcg = (L >> 3) & 1;
    const int vrow_off = (L & 7) + ((L & 8) ? 8 : 0);   // V^T row offset
    const int prow = w * 16 + (L >> 2);            // softmax-owned row
    const int pxr = prow & 7;
    const int arx = arow & 7;

    for (int t = 0; t < 32; t++) {
        const int cur = t & 1;
        if (t + 1 < 32) { kvissue(1 - cur, t + 1); CPA_COMMIT(); CPA_WAIT1(); }
        else { CPA_WAIT0(); }
        __syncthreads();

        const uint32_t khb = sb + SKV0 + cur * KVBUF;
        const uint32_t klb = khb + 8192;
        const uint32_t vhb = khb + 16384;

        // ---- S = Q K^T (3-pass); ks outer so qf loads amortize over np ----
#pragma unroll
        for (int i = 0; i < 8; i++) {
            S[i][0] = 0.0f; S[i][1] = 0.0f; S[i][2] = 0.0f; S[i][3] = 0.0f;
        }
#pragma unroll
        for (int ks = 0; ks < 4; ks++) {
            uint32_t qfh[4], qfl[4];
            uint32_t qoff = arow * 128 + ((((ks * 2 + acg) ^ arx) & 7) << 4);
            ldsm4(qfh, sb + SQHI + qoff);
            ldsm4(qfl, sb + SQLO + qoff);
#pragma unroll
            for (int np = 0; np < 4; np++) {
                int brow = np * 16 + brow_off;
                uint32_t offb = brow * 128 + ((((ks * 2 + bcg) ^ (brow & 7)) & 7) << 4);
                uint32_t kbh[4], kbl[4];
                ldsm4(kbh, khb + offb);
                ldsm4(kbl, klb + offb);
                mma16816(S[2 * np],     qfh, kbh[0], kbh[1]);
                mma16816(S[2 * np + 1], qfh, kbh[2], kbh[3]);
                mma16816(S[2 * np],     qfl, kbh[0], kbh[1]);
                mma16816(S[2 * np + 1], qfl, kbh[2], kbh[3]);
                mma16816(S[2 * np],     qfh, kbl[0], kbl[1]);
                mma16816(S[2 * np + 1], qfh, kbl[2], kbl[3]);
            }
        }

        // ---- online softmax (warp-local rows) ----
        float tm0 = -INFINITY, tm1 = -INFINITY;
#pragma unroll
        for (int i = 0; i < 8; i++) {
            tm0 = fmaxf(tm0, fmaxf(S[i][0], S[i][1]));
            tm1 = fmaxf(tm1, fmaxf(S[i][2], S[i][3]));
        }
        tm0 = fmaxf(tm0, __shfl_xor_sync(0xffffffffu, tm0, 1));
        tm0 = fmaxf(tm0, __shfl_xor_sync(0xffffffffu, tm0, 2));
        tm1 = fmaxf(tm1, __shfl_xor_sync(0xffffffffu, tm1, 1));
        tm1 = fmaxf(tm1, __shfl_xor_sync(0xffffffffu, tm1, 2));
        float mn0 = fmaxf(m0, tm0), mn1 = fmaxf(m1, tm1);
        float sc0 = __expf(m0 - mn0), sc1 = __expf(m1 - mn1);
        l0 *= sc0; l1 *= sc1;
        m0 = mn0; m1 = mn1;
#pragma unroll
        for (int i = 0; i < 8; i++) {
            O[i][0] *= sc0; O[i][1] *= sc0;
            O[i][2] *= sc1; O[i][3] *= sc1;
        }
        {
            uint32_t pb0 = (uint32_t)(SPS + prow * 128 + 4 * (L & 3));
            uint32_t pb1 = pb0 + 8 * 128;
#pragma unroll
            for (int nt = 0; nt < 8; nt++) {
                float p0 = __expf(S[nt][0] - mn0);
                float p1 = __expf(S[nt][1] - mn0);
                float p2 = __expf(S[nt][2] - mn1);
                float p3 = __expf(S[nt][3] - mn1);
                l0 += p0 + p1;
                l1 += p2 + p3;
                __half2 h01 = __floats2half2_rn(p0, p1);
                __half2 h23 = __floats2half2_rn(p2, p3);
                uint32_t gsh = (uint32_t)(((nt ^ pxr) & 7) << 4);
                *(uint32_t*)(smc + pb0 + gsh) = *reinterpret_cast<uint32_t*>(&h01);
                *(uint32_t*)(smc + pb1 + gsh) = *reinterpret_cast<uint32_t*>(&h23);
            }
        }
        __syncwarp();

        // ---- O += P V (1-pass fp16) ----
#pragma unroll
        for (int ks = 0; ks < 4; ks++) {
            uint32_t pa[4];
            uint32_t poff = arow * 128 + ((((ks * 2 + acg) ^ arx) & 7) << 4);
            ldsm4(pa, sb + SPS + poff);
#pragma unroll
            for (int np = 0; np < 4; np++) {
                int vrow = ks * 16 + vrow_off;
                uint32_t voff = vrow * 128 +
                    ((((np * 2 + ((L >> 4) & 1)) ^ (vrow & 7)) & 7) << 4);
                uint32_t vb[4];
                ldsm4t(vb, vhb + voff);
                mma16816(O[2 * np],     pa, vb[0], vb[1]);
                mma16816(O[2 * np + 1], pa, vb[2], vb[3]);
            }
        }
        __syncthreads();   // buf[cur] fully consumed before next prefetch overwrites
    }

    // ---- finalize ----
    l0 += __shfl_xor_sync(0xffffffffu, l0, 1);
    l0 += __shfl_xor_sync(0xffffffffu, l0, 2);
    l1 += __shfl_xor_sync(0xffffffffu, l1, 1);
    l1 += __shfl_xor_sync(0xffffffffu, l1, 2);
    float i0 = 1.0f / l0, i1 = 1.0f / l1;
    int r0 = q0 + prow;
    float* o0 = Out + (rowbase + r0) * D_MODEL + h * HDIM + 2 * (L & 3);
    float* o1 = o0 + 8 * D_MODEL;
#pragma unroll
    for (int nt = 0; nt < 8; nt++) {
        float2 a; a.x = O[nt][0] * i0; a.y = O[nt][1] * i0;
        float2 c; c.x = O[nt][2] * i1; c.y = O[nt][3] * i1;
        *(float2*)(o0 + nt * 8) = a;
        *(float2*)(o1 + nt * 8) = c;
    }
}

// ============================================================================
extern "C" void kernel_launch(void* const* d_in, const int* in_sizes, int n_in,
                              void* d_out, int out_size) {
    (void)in_sizes; (void)n_in; (void)out_size;
    const float* x  = (const float*)d_in[0];
    const float* Wq = (const float*)d_in[1];
    const float* bq = (const float*)d_in[2];
    const float* Wk = (const float*)d_in[3];
    const float* bk = (const float*)d_in[4];
    const float* Wv = (const float*)d_in[5];
    const float* bv = (const float*)d_in[6];
    float* out = (float*)d_out;

    __half *xh, *xl, *wh, *wl, *qh, *ql, *kh, *kl, *vh;
    cudaGetSymbolAddress((void**)&xh, g_Xh);
    cudaGetSymbolAddress((void**)&xl, g_Xl);
    cudaGetSymbolAddress((void**)&wh, g_Wh);
    cudaGetSymbolAddress((void**)&wl, g_Wl);
    cudaGetSymbolAddress((void**)&qh, g_Qhi);
    cudaGetSymbolAddress((void**)&ql, g_Qlo);
    cudaGetSymbolAddress((void**)&kh, g_Khi);
    cudaGetSymbolAddress((void**)&kl, g_Klo);
    cudaGetSymbolAddress((void**)&vh, g_Vhi);

    // Unconditional (idempotent): no static guards allowed in kernel_launch.
    cudaFuncSetAttribute(qkv_hmma, cudaFuncAttributeMaxDynamicSharedMemorySize,
                         GEMM_SMEM);
    cudaFuncSetAttribute(attn_hmma, cudaFuncAttributeMaxDynamicSharedMemorySize,
                         ATTN_SMEM);

    // 1) split inputs to fp16 hi/lo
    const int xn4 = MTOT * D_MODEL / 4;       // 1048576
    const int wn4 = D_MODEL * D_MODEL / 4;    // 262144
    split_x<<<xn4 / 256, 256>>>(x, xh, xl);
    dim3 wgrid(wn4 / 256, 3);
    split_w<<<wgrid, 256>>>(Wq, Wk, Wv, wh, wl);

    // 2) HMMA QKV projection
    dim3 ggrid(24, MTOT / 128);
    qkv_hmma<<<ggrid, 256, GEMM_SMEM>>>(xh, xl, wh, wl, bq, bk, bv,
                                        qh, ql, kh, kl, vh);

    // 3) HMMA flash attention
    dim3 agrid(SEQ / 128, BATCH * NHEADS);
    attn_hmma<<<agrid, 256, ATTN_SMEM>>>(qh, ql, kh, kl, vh, out);
}